// round 13
// baseline (speedup 1.0000x reference)
#include <cuda_runtime.h>
#include <math.h>
#include <stdint.h>

#define BB    8
#define NN    2048
#define DIMC  1024
#define KDIM  2048           // 2*DIMC
#define DR    256
#define NE    4
#define DH    32
#define MTOK  16384          // B*N
#define AST2  36             // A smem row stride (floats) — conflict-free (36 mod 32 = 4)

// ---------------- device scratch (no allocations allowed) ----------------
__device__ float g_Wp[KDIM * DR];      // g-scaled reduce weight, tf32-rounded, PAIR-PERMUTED:
                                       // float idx = (k8*256 + n)*8 + tig*2 + half
                                       // where k = k8*8 + half*4 + tig
__device__ float g_cpart[64 * DR];
__device__ float g_dpart[64 * DR];
__device__ float g_c[DR];
__device__ float g_dv[DR];
__device__ float g_w2bar[NE * 2 * DH];
__device__ float g_b2bar[NE * 2];
__device__ float g_mean[MTOK];
__device__ float g_rstd[MTOK];
__device__ float g_z[(size_t)MTOK * DR];
__device__ float g_px[MTOK];
__device__ float g_pt[MTOK];
__device__ float g_dd[2][BB * DIMC];
__device__ float g_racc[2][BB][DIMC];
__device__ float g_sv[BB][2];
__device__ float g_imp[NE];
__device__ float g_load[NE];
__device__ float4 g_V4[KDIM];
__device__ float  g_rW[KDIM];
__device__ float  g_scal[18];
__device__ float4 g_alpha4[MTOK];
__device__ float g_ox[(size_t)MTOK * DIMC];
__device__ float g_ot[(size_t)MTOK * DIMC];

__device__ __forceinline__ uint32_t f2tf(float v) {
    uint32_t u;
    asm("cvt.rna.tf32.f32 %0, %1;" : "=r"(u) : "f"(v));
    return u;
}

__device__ __forceinline__ float wsum(float v) {
    #pragma unroll
    for (int o = 16; o; o >>= 1) v += __shfl_xor_sync(0xffffffffu, v, o);
    return v;
}

__device__ __forceinline__ void mma16n8k8(float* d, const uint32_t* a, const uint32_t* b) {
    asm volatile("mma.sync.aligned.m16n8k8.row.col.f32.tf32.tf32.f32 "
                 "{%0,%1,%2,%3}, {%4,%5,%6,%7}, {%8,%9}, {%0,%1,%2,%3};\n"
                 : "+f"(d[0]), "+f"(d[1]), "+f"(d[2]), "+f"(d[3])
                 : "r"(a[0]), "r"(a[1]), "r"(a[2]), "r"(a[3]),
                   "r"(b[0]), "r"(b[1]));
}

__device__ __forceinline__ void cpa16(uint32_t smem, const void* gmem) {
    asm volatile("cp.async.cg.shared.global [%0], [%1], 16;" :: "r"(smem), "l"(gmem));
}
__device__ __forceinline__ void cpa_commit() { asm volatile("cp.async.commit_group;"); }
template<int N> __device__ __forceinline__ void cpa_wait() {
    asm volatile("cp.async.wait_group %0;" :: "n"(N));
}

// ---------------- prep1: fold LN1 affine into GEMM weight (tf32-rounded, permuted) ------
__global__ void prep1_kernel(const float* __restrict__ w_red,
                             const float* __restrict__ g1,
                             const float* __restrict__ b1) {
    int j = threadIdx.x;
    int b = blockIdx.x;
    int i0 = b * 32;
    if (b == 0 && j < 18) g_scal[j] = 0.f;
    float ac = 0.f, ad = 0.f;
    for (int ii = 0; ii < 32; ++ii) {
        int i = i0 + ii;
        float w = w_red[(size_t)i * DR + j];
        float wp = __uint_as_float(f2tf(g1[i] * w));
        int k8 = i >> 3, krr = i & 7;
        int tig = krr & 3, half = krr >> 2;
        g_Wp[((size_t)k8 * 256 + j) * 8 + tig * 2 + half] = wp;
        ac += wp;
        ad += b1[i] * w;
    }
    g_cpart[b * DR + j] = ac;
    g_dpart[b * DR + j] = ad;
}

// ---------------- prep2: V rows + ALL scalar folds + (block1) prep0 work ----------------
__global__ void prep2_kernel(const float* __restrict__ w_red,
                             const float* __restrict__ g1,
                             const float* __restrict__ wgate,
                             const int* __restrict__ taskp,
                             const float* __restrict__ g2,
                             const float* __restrict__ lnb2,
                             const float* __restrict__ w2,
                             const float* __restrict__ b2) {
    __shared__ float4 u4[DR];
    __shared__ float4 vred[8];
    __shared__ float  rred[8];
    int tid = threadIdx.x, lane = tid & 31, w = tid >> 5;
    int task = taskp[0];
    {
        int j = tid;
        float gv = g2[j];
        const float* wgp = wgate + (size_t)task * DR * NE + (size_t)j * NE;
        u4[j] = make_float4(gv * wgp[0], gv * wgp[1], gv * wgp[2], gv * wgp[3]);
    }
    __syncthreads();
    int i = blockIdx.x * 8 + w;
    const float* wrow = w_red + (size_t)i * DR + lane * 8;
    float a0 = 0.f, a1 = 0.f, a2 = 0.f, a3 = 0.f, ar = 0.f;
    #pragma unroll
    for (int jj = 0; jj < 8; ++jj) {
        float wv = wrow[jj];
        float4 u = u4[lane * 8 + jj];
        a0 += wv * u.x; a1 += wv * u.y; a2 += wv * u.z; a3 += wv * u.w;
        ar += wv;
    }
    a0 = wsum(a0); a1 = wsum(a1); a2 = wsum(a2); a3 = wsum(a3); ar = wsum(ar);
    if (lane == 0) {
        float gv = g1[i];
        float4 Vr = make_float4(gv * a0, gv * a1, gv * a2, gv * a3);
        float rr = gv * ar * (1.f / 256.f);
        g_V4[i] = Vr;
        g_rW[i] = rr;
        vred[w] = Vr; rred[w] = rr;
    }
    __syncthreads();
    if (tid == 0) {
        float4 s = make_float4(0.f, 0.f, 0.f, 0.f); float sr = 0.f;
        #pragma unroll
        for (int k = 0; k < 8; ++k) {
            s.x += vred[k].x; s.y += vred[k].y; s.z += vred[k].z; s.w += vred[k].w;
            sr += rred[k];
        }
        atomicAdd(&g_scal[0], s.x); atomicAdd(&g_scal[1], s.y);
        atomicAdd(&g_scal[2], s.z); atomicAdd(&g_scal[3], s.w);
        atomicAdd(&g_scal[12], sr);
    }
    if (blockIdx.x == 0) {
        int j = tid;
        float c = 0.f, d = 0.f;
        #pragma unroll 8
        for (int b = 0; b < 64; ++b) {
            c += g_cpart[b * DR + j];
            d += g_dpart[b * DR + j];
        }
        g_c[j] = c; g_dv[j] = d;
        float gv = g2[j], bj = lnb2[j];
        const float* wgp = wgate + (size_t)task * DR * NE + (size_t)j * NE;
        float w0 = wgp[0], w1 = wgp[1], w2v = wgp[2], w3 = wgp[3];
        float vals[13] = { d*gv*w0, d*gv*w1, d*gv*w2v, d*gv*w3,
                           gv*w0, gv*w1, gv*w2v, gv*w3,
                           d * (1.f / 256.f),
                           bj*w0, bj*w1, bj*w2v, bj*w3 };
        const int sidx[13] = {4,5,6,7, 8,9,10,11, 13, 14,15,16,17};
        #pragma unroll
        for (int q = 0; q < 13; ++q) {
            float r = wsum(vals[q]);
            if (lane == 0) atomicAdd(&g_scal[sidx[q]], r);
        }
    }
    if (blockIdx.x == 1) {   // absorbed prep0: zeros + w2bar/b2bar
        if (tid < NE) { g_imp[tid] = 0.f; g_load[tid] = 0.f; }
        if (tid < 2 * BB) ((float*)g_sv)[tid] = 0.f;
        for (int q = tid; q < 2 * BB * DIMC; q += 256) ((float*)g_dd)[q] = 0.f;
        for (int q = tid; q < 2 * BB * DIMC; q += 256) ((float*)g_racc)[q] = 0.f;
        {
            int e = tid >> 6, p = (tid >> 5) & 1, h = tid & 31;
            const float* base = w2 + ((size_t)e * DH + h) * DR + p * 128;
            float s = 0.f;
            for (int o = 0; o < 128; ++o) s += base[o];
            g_w2bar[(e * 2 + p) * DH + h] = s * (1.f / 128.f);
        }
        if (tid < NE * 2) {
            int e = tid >> 1, p = tid & 1;
            const float* base = b2 + (size_t)e * DR + p * 128;
            float s = 0.f;
            for (int o = 0; o < 128; ++o) s += base[o];
            g_b2bar[tid] = s * (1.f / 128.f);
        }
    }
}

// ---------------- rowlogits: ONE pass over x,t -> mean/rstd AND exact alpha ----------------
#define L5ACC(v, kb) { \
    { float4 V = V4s[(kb) + 0]; q0 += v.x * V.x; q1 += v.x * V.y; q2 += v.x * V.z; q3 += v.x * V.w; q4 += v.x * rWs[(kb) + 0]; } \
    { float4 V = V4s[(kb) + 1]; q0 += v.y * V.x; q1 += v.y * V.y; q2 += v.y * V.z; q3 += v.y * V.w; q4 += v.y * rWs[(kb) + 1]; } \
    { float4 V = V4s[(kb) + 2]; q0 += v.z * V.x; q1 += v.z * V.y; q2 += v.z * V.z; q3 += v.z * V.w; q4 += v.z * rWs[(kb) + 2]; } \
    { float4 V = V4s[(kb) + 3]; q0 += v.w * V.x; q1 += v.w * V.y; q2 += v.w * V.z; q3 += v.w * V.w; q4 += v.w * rWs[(kb) + 3]; } }

__global__ __launch_bounds__(256, 2) void rowlogits_kernel(const float* __restrict__ x,
                                                           const float* __restrict__ t) {
    __shared__ float4 V4s[KDIM];
    __shared__ float rWs[KDIM];
    __shared__ float scal[18];
    int tid = threadIdx.x, lane = tid & 31, w = tid >> 5;
    for (int i = tid; i < KDIM; i += 256) { V4s[i] = g_V4[i]; rWs[i] = g_rW[i]; }
    if (tid < 18) scal[tid] = g_scal[tid];
    __syncthreads();
    #pragma unroll 1
    for (int rr = 0; rr < 8; ++rr) {
        int m = blockIdx.x * 64 + w * 8 + rr;
        const float4* xr = (const float4*)(x + (size_t)m * DIMC);
        const float4* tr = (const float4*)(t + (size_t)m * DIMC);
        float q0 = 0.f, q1 = 0.f, q2 = 0.f, q3 = 0.f, q4 = 0.f;
        float s = 0.f, sq = 0.f;
        #pragma unroll 4
        for (int q = 0; q < 8; ++q) {
            int fi = lane + 32 * q;
            float4 v = xr[fi];
            L5ACC(v, fi * 4);
            s += v.x + v.y + v.z + v.w;
            sq += v.x * v.x + v.y * v.y + v.z * v.z + v.w * v.w;
        }
        #pragma unroll 4
        for (int q = 0; q < 8; ++q) {
            int fi = lane + 32 * q;
            float4 v = tr[fi];
            L5ACC(v, 1024 + fi * 4);
            s += v.x + v.y + v.z + v.w;
            sq += v.x * v.x + v.y * v.y + v.z * v.z + v.w * v.w;
        }
        q0 = wsum(q0); q1 = wsum(q1); q2 = wsum(q2); q3 = wsum(q3); q4 = wsum(q4);
        s = wsum(s); sq = wsum(sq);
        if (lane == 0) {
            float mu1 = s * (1.f / 2048.f);
            float var = sq * (1.f / 2048.f) - mu1 * mu1;
            float rs1 = rsqrtf(var + 1e-5f);
            g_mean[m] = mu1;
            g_rstd[m] = rs1;
            float dz0 = rs1 * (q0 - mu1 * scal[0]) + scal[4];
            float dz1 = rs1 * (q1 - mu1 * scal[1]) + scal[5];
            float dz2 = rs1 * (q2 - mu1 * scal[2]) + scal[6];
            float dz3 = rs1 * (q3 - mu1 * scal[3]) + scal[7];
            float mu2 = rs1 * (q4 - mu1 * scal[12]) + scal[13];
            g_alpha4[m] = make_float4(dz0 - mu2 * scal[8], dz1 - mu2 * scal[9],
                                      dz2 - mu2 * scal[10], dz3 - mu2 * scal[11]);
        }
    }
}

// ---------------- tf32 GEMM: K-chunk 32, 3-stage cp.async, packed-pair B ----------------
#define A_STG (128 * AST2)          // 4608 floats / stage
#define B_STG 4096                  // 4 k8 x 128 n x 8 floats
#define GEMM_SMEM_BYTES ((3 * A_STG + 3 * B_STG) * 4)   // 104448

__global__ __launch_bounds__(256, 2) void gemm_tf32_kernel(const float* __restrict__ x,
                                                           const float* __restrict__ t) {
    extern __shared__ float gsm[];
    float* Asm = gsm;                       // 3 stages of [128][AST2]
    float* Bsm = gsm + 3 * A_STG;           // 3 stages of [4][128][8]

    int tid = threadIdx.x;
    int j0 = blockIdx.x * 128;
    int m0 = blockIdx.y * 128;
    int lane = tid & 31, w = tid >> 5;
    int gid = lane >> 2, tig = lane & 3;
    int warpM = (w & 3) * 32, warpN = (w >> 2) * 64;
    int arow = tid >> 1, aqf = (tid & 1) * 16;   // A copy: row, float-offset {0,16}
    int bks = tid >> 6, bnn = (tid & 63) * 2;    // B copy: k8-in-stage, n pair

    uint32_t aDst0 = (uint32_t)__cvta_generic_to_shared(&Asm[arow * AST2 + aqf]);
    uint32_t bDst0 = (uint32_t)__cvta_generic_to_shared(&Bsm[bks * 1024 + bnn * 8]);

    float acc[2][8][4];
    #pragma unroll
    for (int mi = 0; mi < 2; ++mi)
        #pragma unroll
        for (int nf = 0; nf < 8; ++nf)
            #pragma unroll
            for (int r = 0; r < 4; ++r) acc[mi][nf][r] = 0.f;

    // kt in [0,64): 32 K per stage; kt<32 from x, else t
    #define GISSUE(kt, slot) { \
        const float* asrc = ((kt) < 32) ? x : t; \
        const float* ag = asrc + (size_t)(m0 + arow) * DIMC + (((kt) * 32) & 1023) + aqf; \
        uint32_t ad = aDst0 + (slot) * (A_STG * 4); \
        cpa16(ad, ag); cpa16(ad + 16, ag + 4); \
        cpa16(ad + 32, ag + 8); cpa16(ad + 48, ag + 12); \
        const float* bg = g_Wp + ((size_t)((kt) * 4 + bks) * 256 + j0 + bnn) * 8; \
        uint32_t bd = bDst0 + (slot) * (B_STG * 4); \
        cpa16(bd, bg); cpa16(bd + 16, bg + 4); \
        cpa16(bd + 32, bg + 8); cpa16(bd + 48, bg + 12); }

    GISSUE(0, 0); cpa_commit();
    GISSUE(1, 1); cpa_commit();

    int cs = 0;
    #pragma unroll 1
    for (int kt = 0; kt < 64; ++kt) {
        cpa_wait<1>();
        __syncthreads();
        int ns = cs + 2; if (ns >= 3) ns -= 3;
        if (kt < 62) { GISSUE(kt + 2, ns); }
        cpa_commit();

        const float* Ab = Asm + cs * A_STG;
        const float* Bb = Bsm + cs * B_STG;
        #pragma unroll
        for (int ks = 0; ks < 4; ++ks) {
            int ko = ks * 8;
            const float* A0 = Ab + (warpM + gid) * AST2 + ko + tig;
            uint32_t am0[4], am1[4];
            am0[0] = __float_as_uint(A0[0]);
            am0[1] = __float_as_uint(A0[8 * AST2]);
            am0[2] = __float_as_uint(A0[4]);
            am0[3] = __float_as_uint(A0[8 * AST2 + 4]);
            am1[0] = __float_as_uint(A0[16 * AST2]);
            am1[1] = __float_as_uint(A0[24 * AST2]);
            am1[2] = __float_as_uint(A0[16 * AST2 + 4]);
            am1[3] = __float_as_uint(A0[24 * AST2 + 4]);
            const float* B0 = Bb + ks * 1024 + (warpN + gid) * 8 + tig * 2;
            #pragma unroll
            for (int nf = 0; nf < 8; ++nf) {
                uint2 bb = *(const uint2*)(B0 + nf * 64);
                uint32_t br[2] = {bb.x, bb.y};
                mma16n8k8(acc[0][nf], am0, br);
                mma16n8k8(acc[1][nf], am1, br);
            }
        }
        if (++cs == 3) cs = 0;
    }

    // epilogue: LN1 correction + store z
    float cj[16], dj[16];
    #pragma unroll
    for (int nf = 0; nf < 8; ++nf) {
        int colG = j0 + warpN + nf * 8 + 2 * tig;
        float2 cc = *(const float2*)&g_c[colG];
        float2 dd = *(const float2*)&g_dv[colG];
        cj[nf * 2] = cc.x; cj[nf * 2 + 1] = cc.y;
        dj[nf * 2] = dd.x; dj[nf * 2 + 1] = dd.y;
    }
    #pragma unroll
    for (int mi = 0; mi < 2; ++mi) {
        #pragma unroll
        for (int h = 0; h < 2; ++h) {
            int row = m0 + warpM + mi * 16 + h * 8 + gid;
            float mu = g_mean[row];
            float rs = g_rstd[row];
            float* zp = g_z + (size_t)row * DR + j0 + warpN;
            #pragma unroll
            for (int nf = 0; nf < 8; ++nf) {
                float v0 = acc[mi][nf][h * 2 + 0];
                float v1 = acc[mi][nf][h * 2 + 1];
                float2 o;
                o.x = rs * (v0 - mu * cj[nf * 2 + 0]) + dj[nf * 2 + 0];
                o.y = rs * (v1 - mu * cj[nf * 2 + 1]) + dj[nf * 2 + 1];
                *(float2*)&zp[nf * 8 + 2 * tig] = o;
            }
        }
    }
}

// ---------------- MoE: 64-row tiles, (2-row x 4-h) blocking ----------------
#define MOE_SMEM_FLOATS (64 * 257 + 8192 + 256 + 256 + 256 + 4 + 4)

__global__ __launch_bounds__(256, 2) void moe_kernel(const float* __restrict__ g2,
                                                     const float* __restrict__ b2g,
                                                     const float* __restrict__ w1,
                                                     const float* __restrict__ b1e) {
    extern __shared__ float sm[];
    float* yf    = sm;                  // 64 x 257
    float* w1s   = yf + 64 * 257;       // 8192
    float* g2s   = w1s + 8192;          // 256
    float* b2s   = g2s + 256;           // 256
    float* gates = b2s + 256;           // 64 x 4
    float* sImp  = gates + 256;
    float* sLoad = sImp + 4;
    __shared__ float betas[4];

    int tid = threadIdx.x, lane = tid & 31, w = tid >> 5;
    int m0 = blockIdx.x * 64;

    g2s[tid] = g2[tid];
    b2s[tid] = b2g[tid];
    if (tid < 4) betas[tid] = g_scal[14 + tid];
    if (tid < 8) { sImp[tid & 3] = 0.f; sLoad[tid & 3] = 0.f; }
    __syncthreads();

    for (int rr = 0; rr < 8; ++rr) {
        int r = w * 8 + rr;
        int m = m0 + r;
        const float* zr = g_z + (size_t)m * DR;
        float ev[8];
        float s = 0.f, sq = 0.f;
        #pragma unroll
        for (int i = 0; i < 8; ++i) {
            float v = zr[lane + 32 * i];
            ev[i] = v; s += v; sq += v * v;
        }
        s = wsum(s); sq = wsum(sq);
        float muv = s * (1.f / 256.f);
        float rsv = rsqrtf(sq * (1.f / 256.f) - muv * muv + 1e-5f);
        #pragma unroll
        for (int i = 0; i < 8; ++i) {
            int j = lane + 32 * i;
            yf[r * 257 + j] = (ev[i] - muv) * rsv * g2s[j] + b2s[j];
        }
        if (lane == 0) {
            float4 al = g_alpha4[m];
            float lv[4] = {rsv * al.x + betas[0], rsv * al.y + betas[1],
                           rsv * al.z + betas[2], rsv * al.w + betas[3]};
            int i0 = 0; float v0 = lv[0];
            #pragma unroll
            for (int e = 1; e < 4; ++e) if (lv[e] > v0) { v0 = lv[e]; i0 = e; }
            int i1 = -1; float v1 = -1e30f;
            #pragma unroll
            for (int e = 0; e < 4; ++e) if (e != i0 && lv[e] > v1) { v1 = lv[e]; i1 = e; }
            float ex = __expf(v1 - v0);
            float inv = 1.f / (1.f + ex);
            float ga = inv, gb = ex * inv;
            gates[r * 4 + 0] = 0.f; gates[r * 4 + 1] = 0.f;
            gates[r * 4 + 2] = 0.f; gates[r * 4 + 3] = 0.f;
            gates[r * 4 + i0] = ga;
            gates[r * 4 + i1] = gb;
            atomicAdd(&sImp[i0], ga);  atomicAdd(&sImp[i1], gb);
            atomicAdd(&sLoad[i0], 1.f); atomicAdd(&sLoad[i1], 1.f);
        }
    }
    __syncthreads();
    if (tid < 4) {
        atomicAdd(&g_imp[tid], sImp[tid]);
        atomicAdd(&g_load[tid], sLoad[tid]);
    }

    int rp = tid >> 3;          // 0..31 row-pair
    int hq = (tid & 7) * 4;     // hidden base
    int ra = rp * 2, rb = ra + 1;
    float rowPXa = 0.f, rowPTa = 0.f, rowPXb = 0.f, rowPTb = 0.f;
    for (int e = 0; e < NE; ++e) {
        __syncthreads();
        const float* w1p = w1 + (size_t)e * (DR * DH);
        #pragma unroll
        for (int q = 0; q < 32; ++q) w1s[tid + 256 * q] = w1p[tid + 256 * q];
        __syncthreads();
        float fa[4], fb[4];
        #pragma unroll
        for (int i = 0; i < 4; ++i) {
            float bv = b1e[e * DH + hq + i];
            fa[i] = bv; fb[i] = bv;
        }
        const float* yra = yf + ra * 257;
        const float* yrb = yf + rb * 257;
        #pragma unroll 4
        for (int k = 0; k < 256; ++k) {
            float ya = yra[k], yb = yrb[k];
            float4 wv = *(const float4*)&w1s[k * 32 + hq];
            fa[0] += ya * wv.x; fa[1] += ya * wv.y; fa[2] += ya * wv.z; fa[3] += ya * wv.w;
            fb[0] += yb * wv.x; fb[1] += yb * wv.y; fb[2] += yb * wv.z; fb[3] += yb * wv.w;
        }
        float pxa = 0.f, pta = 0.f, pxb = 0.f, ptb = 0.f;
        #pragma unroll
        for (int i = 0; i < 4; ++i) {
            float wx = g_w2bar[(e * 2 + 0) * DH + hq + i];
            float wt = g_w2bar[(e * 2 + 1) * DH + hq + i];
            float ha = fmaxf(fa[i], 0.f), hb = fmaxf(fb[i], 0.f);
            pxa += ha * wx; pta += ha * wt;
            pxb += hb * wx; ptb += hb * wt;
        }
        #pragma unroll
        for (int o = 1; o < 8; o <<= 1) {
            pxa += __shfl_xor_sync(0xffffffffu, pxa, o);
            pta += __shfl_xor_sync(0xffffffffu, pta, o);
            pxb += __shfl_xor_sync(0xffffffffu, pxb, o);
            ptb += __shfl_xor_sync(0xffffffffu, ptb, o);
        }
        float gva = gates[ra * 4 + e], gvb = gates[rb * 4 + e];
        rowPXa += gva * (pxa + g_b2bar[e * 2 + 0]);
        rowPTa += gva * (pta + g_b2bar[e * 2 + 1]);
        rowPXb += gvb * (pxb + g_b2bar[e * 2 + 0]);
        rowPTb += gvb * (ptb + g_b2bar[e * 2 + 1]);
    }
    if ((tid & 7) == 0) {
        g_px[m0 + ra] = 1.f / (1.f + expf(-rowPXa));
        g_pt[m0 + ra] = 1.f / (1.f + expf(-rowPTa));
        g_px[m0 + rb] = 1.f / (1.f + expf(-rowPXb));
        g_pt[m0 + rb] = 1.f / (1.f + expf(-rowPTb));
    }
}

// ---------------- aux loss (scalar) ----------------
__global__ void aux_kernel(float* auxp) {
    if (threadIdx.x == 0) {
        float mi = 0.f, ml = 0.f;
        #pragma unroll
        for (int e = 0; e < NE; ++e) { mi += g_imp[e]; ml += g_load[e]; }
        mi *= 0.25f; ml *= 0.25f;
        float vi = 0.f, vl = 0.f;
        #pragma unroll
        for (int e = 0; e < NE; ++e) {
            float a = g_imp[e] - mi; vi += a * a;
            float b = g_load[e] - ml; vl += b * b;
        }
        vi *= 0.25f; vl *= 0.25f;
        auxp[0] = vi / (mi * mi + 1e-10f) + vl / (ml * ml + 1e-10f);
    }
}

// ---------------- out_x/out_t + |diff| reduction (lane-consecutive) ----------------
__global__ void outxt_kernel(const float* __restrict__ x, const float* __restrict__ t,
                             const float* __restrict__ past_x, const float* __restrict__ past_t,
                             const float* __restrict__ modal, const int* __restrict__ taskp,
                             float* __restrict__ ox, float* __restrict__ ot) {
    int tid = threadIdx.x;
    int nt = blockIdx.x;  // 128 n-tiles of 16
    int b = blockIdx.y;   // 8
    int task = taskp[0];
    float msx[4], mst[4], A1[4], A2[4];
    const float* mx = modal + (size_t)(task * 2 + 0) * DIMC;
    const float* mt = modal + (size_t)(task * 2 + 1) * DIMC;
    #pragma unroll
    for (int q = 0; q < 4; ++q) {
        msx[q] = mx[tid + 256 * q];
        mst[q] = mt[tid + 256 * q];
        A1[q] = 0.f; A2[q] = 0.f;
    }
    for (int nn = 0; nn < 16; ++nn) {
        size_t m = (size_t)b * NN + nt * 16 + nn;
        size_t row = m * DIMC;
        float p1 = g_px[m], p2 = g_pt[m];
        #pragma unroll
        for (int q = 0; q < 4; ++q) {
            size_t idx = row + tid + 256 * q;
            float vx = p1 * x[idx] + msx[q];
            float vt = p2 * t[idx] + mst[q];
            ox[idx] = vx;
            ot[idx] = vt;
            A1[q] += fabsf(vx - past_x[idx]);
            A2[q] += fabsf(vt - past_t[idx]);
        }
    }
    #pragma unroll
    for (int q = 0; q < 4; ++q) {
        atomicAdd(&g_dd[0][b * DIMC + tid + 256 * q], A1[q]);
        atomicAdd(&g_dd[1][b * DIMC + tid + 256 * q], A2[q]);
    }
}

// ---------------- scoreA: hidden = d @ ws1 partials ----------------
__global__ void scoreA_kernel(const float* __restrict__ ws1) {
    __shared__ float ds[2][8][128];
    int tid = threadIdx.x;
    int ic = blockIdx.x;
    int jc = blockIdx.y;
    for (int q = tid; q < 2048; q += 256) {
        int s = q >> 10, rem = q & 1023;
        int bb = rem >> 7, i = rem & 127;
        ds[s][bb][i] = g_dd[s][bb * DIMC + ic * 128 + i] * (1.f / 2048.f);
    }
    __syncthreads();
    int j = jc * 256 + tid;
    float acc0[8], acc1[8];
    #pragma unroll
    for (int bb = 0; bb < 8; ++bb) { acc0[bb] = 0.f; acc1[bb] = 0.f; }
    const float* wp = ws1 + (size_t)(ic * 128) * DIMC + j;
    #pragma unroll 4
    for (int i = 0; i < 128; ++i) {
        float wv = wp[(size_t)i * DIMC];
        #pragma unroll
        for (int bb = 0; bb < 8; ++bb) {
            acc0[bb] += ds[0][bb][i] * wv;
            acc1[bb] += ds[1][bb][i] * wv;
        }
    }
    #pragma unroll
    for (int bb = 0; bb < 8; ++bb) {
        atomicAdd(&g_racc[0][bb][j], acc0[bb]);
        atomicAdd(&g_racc[1][bb][j], acc1[bb]);
    }
}

// ---------------- scoreB: s = relu(hidden) @ ws2 ----------------
__global__ void scoreB_kernel(const float* __restrict__ ws2) {
    __shared__ float r1s[256], r2s[256];
    int b = blockIdx.x, tid = threadIdx.x;
    float s1 = 0.f, s2 = 0.f;
    #pragma unroll
    for (int q = 0; q < 4; ++q) {
        int j = tid + 256 * q;
        float w2v = ws2[j];
        s1 += fmaxf(g_racc[0][b][j], 0.f) * w2v;
        s2 += fmaxf(g_racc[1][b][j], 0.f) * w2v;
    }
    r1s[tid] = s1; r2s[tid] = s2;
    __syncthreads();
    for (int o = 128; o; o >>= 1) {
        if (tid < o) { r1s[tid] += r1s[tid + o]; r2s[tid] += r2s[tid + o]; }
        __syncthreads();
    }
    if (tid == 0) { g_sv[b][0] = r1s[0]; g_sv[b][1] = r2s[0]; }
}

// ---------------- final combine: recompute from aligned x,t ----------------
__global__ void combine_kernel(const float* __restrict__ x, const float* __restrict__ t,
                               const float* __restrict__ modal, const int* __restrict__ taskp,
                               float* __restrict__ out) {
    int tid = threadIdx.x;
    int nt = blockIdx.x;   // 64 tiles of 32 rows
    int b = blockIdx.y;    // 8
    int task = taskp[0];
    float s1 = g_sv[b][0], s2 = g_sv[b][1];
    float mx = fmaxf(s1, s2);
    float e1 = expf(s1 - mx), e2 = expf(s2 - mx);
    float inv = 1.f / (e1 + e2);
    float w0 = e1 * inv, w1 = e2 * inv;
    float4 msx = ((const float4*)(modal + (size_t)(task * 2 + 0) * DIMC))[tid];
    float4 mst = ((const float4*)(modal + (size_t)(task * 2 + 1) * DIMC))[tid];
    float4 cm;
    cm.x = w1 * msx.x + w0 * mst.x; cm.y = w1 * msx.y + w0 * mst.y;
    cm.z = w1 * msx.z + w0 * mst.z; cm.w = w1 * msx.w + w0 * mst.w;
    for (int nn = 0; nn < 32; ++nn) {
        size_t m = (size_t)b * NN + nt * 32 + nn;
        size_t ro = m * (DIMC / 4) + tid;
        float c1 = w1 * g_px[m], c2 = w0 * g_pt[m];
        float4 xv = ((const float4*)x)[ro];
        float4 tv = ((const float4*)t)[ro];
        float4 o;
        o.x = c1 * xv.x + c2 * tv.x + cm.x;
        o.y = c1 * xv.y + c2 * tv.y + cm.y;
        o.z = c1 * xv.z + c2 * tv.z + cm.z;
        o.w = c1 * xv.w + c2 * tv.w + cm.w;
        ((float4*)out)[ro] = o;
    }
}

// ---------------- launch (gemm at launch index 3 -> ncu-profiled) ----------------
extern "C" void kernel_launch(void* const* d_in, const int* in_sizes, int n_in,
                              void* d_out, int out_size) {
    const float* x      = (const float*)d_in[0];
    const float* t      = (const float*)d_in[1];
    const float* past_x = (const float*)d_in[2];
    const float* past_t = (const float*)d_in[3];
    const int*   taskp  = (const int*)  d_in[4];
    const float* ln1_g  = (const float*)d_in[5];
    const float* ln1_b  = (const float*)d_in[6];
    const float* w_red  = (const float*)d_in[7];
    const float* ln2_g  = (const float*)d_in[8];
    const float* ln2_b  = (const float*)d_in[9];
    const float* w_gate = (const float*)d_in[10];
    const float* w1     = (const float*)d_in[11];
    const float* b1e    = (const float*)d_in[12];
    const float* w2     = (const float*)d_in[13];
    const float* b2     = (const float*)d_in[14];
    const float* modal  = (const float*)d_in[15];
    const float* ws1    = (const float*)d_in[16];
    const float* ws2    = (const float*)d_in[17];

    float* out = (float*)d_out;
    const size_t OUTN = (size_t)MTOK * DIMC;
    bool full = ((size_t)(unsigned)out_size >= 3 * OUTN + 1);

    float *ox, *ot;
    if (full) {
        ox = out + OUTN + 1;     // layout: out | aux | out_x | out_t (4B-aligned only!)
        ot = ox + OUTN;
    } else {
        void* p;
        cudaGetSymbolAddress(&p, g_ox); ox = (float*)p;
        cudaGetSymbolAddress(&p, g_ot); ot = (float*)p;
    }

    prep1_kernel<<<64, 256>>>(w_red, ln1_g, ln1_b);                               // idx 0
    prep2_kernel<<<256, 256>>>(w_red, ln1_g, w_gate, taskp, ln2_g, ln2_b, w2, b2); // idx 1
    rowlogits_kernel<<<256, 256>>>(x, t);                                         // idx 2

    cudaFuncSetAttribute(gemm_tf32_kernel, cudaFuncAttributeMaxDynamicSharedMemorySize,
                         GEMM_SMEM_BYTES);
    gemm_tf32_kernel<<<dim3(2, 128), 256, GEMM_SMEM_BYTES>>>(x, t);               // idx 3 <- profiled

    const int moe_smem = MOE_SMEM_FLOATS * (int)sizeof(float);
    cudaFuncSetAttribute(moe_kernel, cudaFuncAttributeMaxDynamicSharedMemorySize, moe_smem);
    moe_kernel<<<256, 256, moe_smem>>>(ln2_g, ln2_b, w1, b1e);                    // idx 4

    if (full) aux_kernel<<<1, 32>>>(out + OUTN);
    outxt_kernel<<<dim3(128, 8), 256>>>(x, t, past_x, past_t, modal, taskp, ox, ot);
    scoreA_kernel<<<dim3(8, 4), 256>>>(ws1);
    scoreB_kernel<<<8, 256>>>(ws2);
    combine_kernel<<<dim3(64, 8), 256>>>(x, t, modal, taskp, out);
}

// round 17
// speedup vs baseline: 1.5022x; 1.5022x over previous
#include <cuda_runtime.h>
#include <math.h>
#include <stdint.h>

#define BB    8
#define NN    2048
#define DIMC  1024
#define KDIM  2048           // 2*DIMC
#define DR    256
#define NE    4
#define DH    32
#define MTOK  16384          // B*N
#define AST   20             // A smem row stride (floats) — conflict-free, 16B-aligned

// ---------------- device scratch (no allocations allowed) ----------------
__device__ float g_Wp[KDIM * DR];      // g-scaled reduce weight, tf32-rounded, PAIR-PERMUTED:
                                       // float idx = ((i>>3)*256 + n)*8 + tig*2 + half
                                       // where i = (i>>3)*8 + half*4 + tig
__device__ float g_cpart[64 * DR];
__device__ float g_dpart[64 * DR];
__device__ float g_c[DR];
__device__ float g_dv[DR];
__device__ float g_w2bar[NE * 2 * DH];
__device__ float g_b2bar[NE * 2];
__device__ float g_mean[MTOK];
__device__ float g_rstd[MTOK];
__device__ float g_z[(size_t)MTOK * DR];
__device__ float g_px[MTOK];
__device__ float g_pt[MTOK];
__device__ float g_dd[2][BB * DIMC];
__device__ float g_racc[2][BB][DIMC];
__device__ float g_sv[BB][2];
__device__ float g_imp[NE];
__device__ float g_load[NE];
__device__ float4 g_V4[KDIM];
__device__ float  g_rW[KDIM];
__device__ float  g_scal[18];
__device__ float4 g_alpha4[MTOK];
__device__ float g_ox[(size_t)MTOK * DIMC];
__device__ float g_ot[(size_t)MTOK * DIMC];

__device__ __forceinline__ uint32_t f2tf(float v) {
    uint32_t u;
    asm("cvt.rna.tf32.f32 %0, %1;" : "=r"(u) : "f"(v));
    return u;
}

__device__ __forceinline__ float wsum(float v) {
    #pragma unroll
    for (int o = 16; o; o >>= 1) v += __shfl_xor_sync(0xffffffffu, v, o);
    return v;
}

__device__ __forceinline__ void mma16n8k8(float* d, const uint32_t* a, const uint32_t* b) {
    asm volatile("mma.sync.aligned.m16n8k8.row.col.f32.tf32.tf32.f32 "
                 "{%0,%1,%2,%3}, {%4,%5,%6,%7}, {%8,%9}, {%0,%1,%2,%3};\n"
                 : "+f"(d[0]), "+f"(d[1]), "+f"(d[2]), "+f"(d[3])
                 : "r"(a[0]), "r"(a[1]), "r"(a[2]), "r"(a[3]),
                   "r"(b[0]), "r"(b[1]));
}

__device__ __forceinline__ void cpa16(uint32_t smem, const void* gmem) {
    asm volatile("cp.async.cg.shared.global [%0], [%1], 16;" :: "r"(smem), "l"(gmem));
}
__device__ __forceinline__ void cpa_commit() { asm volatile("cp.async.commit_group;"); }
template<int N> __device__ __forceinline__ void cpa_wait() {
    asm volatile("cp.async.wait_group %0;" :: "n"(N));
}

// ---------------- prep1: fold LN1 affine into GEMM weight (tf32-rounded, permuted) ------
__global__ void prep1_kernel(const float* __restrict__ w_red,
                             const float* __restrict__ g1,
                             const float* __restrict__ b1) {
    int j = threadIdx.x;
    int b = blockIdx.x;
    int i0 = b * 32;
    if (b == 0 && j < 18) g_scal[j] = 0.f;
    float ac = 0.f, ad = 0.f;
    for (int ii = 0; ii < 32; ++ii) {
        int i = i0 + ii;
        float w = w_red[(size_t)i * DR + j];
        float wp = __uint_as_float(f2tf(g1[i] * w));
        int k8 = i >> 3, krr = i & 7;
        int tig = krr & 3, half = krr >> 2;
        g_Wp[((size_t)k8 * 256 + j) * 8 + tig * 2 + half] = wp;
        ac += wp;
        ad += b1[i] * w;
    }
    g_cpart[b * DR + j] = ac;
    g_dpart[b * DR + j] = ad;
}

// ---------------- prep2: V rows + ALL scalar folds + (block1) prep0 work ----------------
__global__ void prep2_kernel(const float* __restrict__ w_red,
                             const float* __restrict__ g1,
                             const float* __restrict__ wgate,
                             const int* __restrict__ taskp,
                             const float* __restrict__ g2,
                             const float* __restrict__ lnb2,
                             const float* __restrict__ w2,
                             const float* __restrict__ b2) {
    __shared__ float4 u4[DR];
    __shared__ float4 vred[8];
    __shared__ float  rred[8];
    int tid = threadIdx.x, lane = tid & 31, w = tid >> 5;
    int task = taskp[0];
    {
        int j = tid;
        float gv = g2[j];
        const float* wgp = wgate + (size_t)task * DR * NE + (size_t)j * NE;
        u4[j] = make_float4(gv * wgp[0], gv * wgp[1], gv * wgp[2], gv * wgp[3]);
    }
    __syncthreads();
    int i = blockIdx.x * 8 + w;
    const float* wrow = w_red + (size_t)i * DR + lane * 8;
    float a0 = 0.f, a1 = 0.f, a2 = 0.f, a3 = 0.f, ar = 0.f;
    #pragma unroll
    for (int jj = 0; jj < 8; ++jj) {
        float wv = wrow[jj];
        float4 u = u4[lane * 8 + jj];
        a0 += wv * u.x; a1 += wv * u.y; a2 += wv * u.z; a3 += wv * u.w;
        ar += wv;
    }
    a0 = wsum(a0); a1 = wsum(a1); a2 = wsum(a2); a3 = wsum(a3); ar = wsum(ar);
    if (lane == 0) {
        float gv = g1[i];
        float4 Vr = make_float4(gv * a0, gv * a1, gv * a2, gv * a3);
        float rr = gv * ar * (1.f / 256.f);
        g_V4[i] = Vr;
        g_rW[i] = rr;
        vred[w] = Vr; rred[w] = rr;
    }
    __syncthreads();
    if (tid == 0) {
        float4 s = make_float4(0.f, 0.f, 0.f, 0.f); float sr = 0.f;
        #pragma unroll
        for (int k = 0; k < 8; ++k) {
            s.x += vred[k].x; s.y += vred[k].y; s.z += vred[k].z; s.w += vred[k].w;
            sr += rred[k];
        }
        atomicAdd(&g_scal[0], s.x); atomicAdd(&g_scal[1], s.y);
        atomicAdd(&g_scal[2], s.z); atomicAdd(&g_scal[3], s.w);
        atomicAdd(&g_scal[12], sr);
    }
    if (blockIdx.x == 0) {
        int j = tid;
        float c = 0.f, d = 0.f;
        #pragma unroll 8
        for (int b = 0; b < 64; ++b) {
            c += g_cpart[b * DR + j];
            d += g_dpart[b * DR + j];
        }
        g_c[j] = c; g_dv[j] = d;
        float gv = g2[j], bj = lnb2[j];
        const float* wgp = wgate + (size_t)task * DR * NE + (size_t)j * NE;
        float w0 = wgp[0], w1 = wgp[1], w2v = wgp[2], w3 = wgp[3];
        float vals[13] = { d*gv*w0, d*gv*w1, d*gv*w2v, d*gv*w3,
                           gv*w0, gv*w1, gv*w2v, gv*w3,
                           d * (1.f / 256.f),
                           bj*w0, bj*w1, bj*w2v, bj*w3 };
        const int sidx[13] = {4,5,6,7, 8,9,10,11, 13, 14,15,16,17};
        #pragma unroll
        for (int q = 0; q < 13; ++q) {
            float r = wsum(vals[q]);
            if (lane == 0) atomicAdd(&g_scal[sidx[q]], r);
        }
    }
    if (blockIdx.x == 1) {   // absorbed prep0: zeros + w2bar/b2bar
        if (tid < NE) { g_imp[tid] = 0.f; g_load[tid] = 0.f; }
        if (tid < 2 * BB) ((float*)g_sv)[tid] = 0.f;
        for (int q = tid; q < 2 * BB * DIMC; q += 256) ((float*)g_dd)[q] = 0.f;
        for (int q = tid; q < 2 * BB * DIMC; q += 256) ((float*)g_racc)[q] = 0.f;
        {
            int e = tid >> 6, p = (tid >> 5) & 1, h = tid & 31;
            const float* base = w2 + ((size_t)e * DH + h) * DR + p * 128;
            float s = 0.f;
            for (int o = 0; o < 128; ++o) s += base[o];
            g_w2bar[(e * 2 + p) * DH + h] = s * (1.f / 128.f);
        }
        if (tid < NE * 2) {
            int e = tid >> 1, p = tid & 1;
            const float* base = b2 + (size_t)e * DR + p * 128;
            float s = 0.f;
            for (int o = 0; o < 128; ++o) s += base[o];
            g_b2bar[tid] = s * (1.f / 128.f);
        }
    }
}

// ---------------- rowlogits: ONE pass over x,t -> mean/rstd AND exact alpha ----------------
#define L5ACC(v, kb) { \
    { float4 V = V4s[(kb) + 0]; q0 += v.x * V.x; q1 += v.x * V.y; q2 += v.x * V.z; q3 += v.x * V.w; q4 += v.x * rWs[(kb) + 0]; } \
    { float4 V = V4s[(kb) + 1]; q0 += v.y * V.x; q1 += v.y * V.y; q2 += v.y * V.z; q3 += v.y * V.w; q4 += v.y * rWs[(kb) + 1]; } \
    { float4 V = V4s[(kb) + 2]; q0 += v.z * V.x; q1 += v.z * V.y; q2 += v.z * V.z; q3 += v.z * V.w; q4 += v.z * rWs[(kb) + 2]; } \
    { float4 V = V4s[(kb) + 3]; q0 += v.w * V.x; q1 += v.w * V.y; q2 += v.w * V.z; q3 += v.w * V.w; q4 += v.w * rWs[(kb) + 3]; } }

__global__ __launch_bounds__(256, 2) void rowlogits_kernel(const float* __restrict__ x,
                                                           const float* __restrict__ t) {
    __shared__ float4 V4s[KDIM];
    __shared__ float rWs[KDIM];
    __shared__ float scal[18];
    int tid = threadIdx.x, lane = tid & 31, w = tid >> 5;
    for (int i = tid; i < KDIM; i += 256) { V4s[i] = g_V4[i]; rWs[i] = g_rW[i]; }
    if (tid < 18) scal[tid] = g_scal[tid];
    __syncthreads();
    #pragma unroll 1
    for (int rr = 0; rr < 8; ++rr) {
        int m = blockIdx.x * 64 + w * 8 + rr;
        const float4* xr = (const float4*)(x + (size_t)m * DIMC);
        const float4* tr = (const float4*)(t + (size_t)m * DIMC);
        float q0 = 0.f, q1 = 0.f, q2 = 0.f, q3 = 0.f, q4 = 0.f;
        float s = 0.f, sq = 0.f;
        #pragma unroll 4
        for (int q = 0; q < 8; ++q) {
            int fi = lane + 32 * q;
            float4 v = xr[fi];
            L5ACC(v, fi * 4);
            s += v.x + v.y + v.z + v.w;
            sq += v.x * v.x + v.y * v.y + v.z * v.z + v.w * v.w;
        }
        #pragma unroll 4
        for (int q = 0; q < 8; ++q) {
            int fi = lane + 32 * q;
            float4 v = tr[fi];
            L5ACC(v, 1024 + fi * 4);
            s += v.x + v.y + v.z + v.w;
            sq += v.x * v.x + v.y * v.y + v.z * v.z + v.w * v.w;
        }
        q0 = wsum(q0); q1 = wsum(q1); q2 = wsum(q2); q3 = wsum(q3); q4 = wsum(q4);
        s = wsum(s); sq = wsum(sq);
        if (lane == 0) {
            float mu1 = s * (1.f / 2048.f);
            float var = sq * (1.f / 2048.f) - mu1 * mu1;
            float rs1 = rsqrtf(var + 1e-5f);
            g_mean[m] = mu1;
            g_rstd[m] = rs1;
            float dz0 = rs1 * (q0 - mu1 * scal[0]) + scal[4];
            float dz1 = rs1 * (q1 - mu1 * scal[1]) + scal[5];
            float dz2 = rs1 * (q2 - mu1 * scal[2]) + scal[6];
            float dz3 = rs1 * (q3 - mu1 * scal[3]) + scal[7];
            float mu2 = rs1 * (q4 - mu1 * scal[12]) + scal[13];
            g_alpha4[m] = make_float4(dz0 - mu2 * scal[8], dz1 - mu2 * scal[9],
                                      dz2 - mu2 * scal[10], dz3 - mu2 * scal[11]);
        }
    }
}

// ---------------- tf32 GEMM (R12 config): K16, 4-stage cp.async, packed-pair B ----------
#define A_STAGE_F (128 * AST)       // 2560 floats / stage
#define B_STAGE_F 2048              // 2 ks x 128 n x 8 floats
#define GEMM_SMEM_BYTES ((4 * A_STAGE_F + 4 * B_STAGE_F) * 4)   // 73728

__global__ __launch_bounds__(256, 2) void gemm_tf32_kernel(const float* __restrict__ x,
                                                           const float* __restrict__ t) {
    extern __shared__ float gsm[];
    float* Asm = gsm;                       // 4 stages of [128][AST]
    float* Bsm = gsm + 4 * A_STAGE_F;       // 4 stages of [2][128][8]

    int tid = threadIdx.x;
    int j0 = blockIdx.x * 128;
    int m0 = blockIdx.y * 128;
    int lane = tid & 31, w = tid >> 5;
    int gid = lane >> 2, tig = lane & 3;
    int warpM = (w & 3) * 32, warpN = (w >> 2) * 64;
    int arow = tid >> 1, aq = (tid & 1) * 8;   // A copy: row, float-offset {0,8}
    int bks = tid >> 7, bnn = tid & 127;       // B copy: ks, n-within-tile

    uint32_t aDst0 = (uint32_t)__cvta_generic_to_shared(&Asm[arow * AST + aq]);
    uint32_t bDst0 = (uint32_t)__cvta_generic_to_shared(&Bsm[bks * 1024 + bnn * 8]);

    float acc[2][8][4];
    #pragma unroll
    for (int mi = 0; mi < 2; ++mi)
        #pragma unroll
        for (int nf = 0; nf < 8; ++nf)
            #pragma unroll
            for (int r = 0; r < 4; ++r) acc[mi][nf][r] = 0.f;

    #define GISSUE(kt, slot) { \
        const float* asrc = ((kt) < 64) ? x : t; \
        const float* ag = asrc + (size_t)(m0 + arow) * DIMC + (((kt) * 16) & 1023) + aq; \
        uint32_t ad = aDst0 + (slot) * (A_STAGE_F * 4); \
        cpa16(ad, ag); cpa16(ad + 16, ag + 4); \
        const float* bg = g_Wp + ((size_t)((kt) * 2 + bks) * 256 + j0 + bnn) * 8; \
        uint32_t bd = bDst0 + (slot) * (B_STAGE_F * 4); \
        cpa16(bd, bg); cpa16(bd + 16, bg + 4); }

    GISSUE(0, 0); cpa_commit();
    GISSUE(1, 1); cpa_commit();
    GISSUE(2, 2); cpa_commit();

    int cs = 0;
    #pragma unroll 1
    for (int kt = 0; kt < 128; ++kt) {
        cpa_wait<2>();
        __syncthreads();
        int ns = cs + 3; if (ns >= 4) ns -= 4;
        if (kt < 125) { GISSUE(kt + 3, ns); }
        cpa_commit();

        const float* Ab = Asm + cs * A_STAGE_F;
        const float* Bb = Bsm + cs * B_STAGE_F;
        #pragma unroll
        for (int ks = 0; ks < 2; ++ks) {
            int ko = ks * 8;
            const float* A0 = Ab + (warpM + gid) * AST + ko + tig;
            uint32_t am0[4], am1[4];
            am0[0] = __float_as_uint(A0[0]);
            am0[1] = __float_as_uint(A0[8 * AST]);
            am0[2] = __float_as_uint(A0[4]);
            am0[3] = __float_as_uint(A0[8 * AST + 4]);
            am1[0] = __float_as_uint(A0[16 * AST]);
            am1[1] = __float_as_uint(A0[24 * AST]);
            am1[2] = __float_as_uint(A0[16 * AST + 4]);
            am1[3] = __float_as_uint(A0[24 * AST + 4]);
            const float* B0 = Bb + ks * 1024 + (warpN + gid) * 8 + tig * 2;
            #pragma unroll
            for (int nf = 0; nf < 8; ++nf) {
                uint2 bb = *(const uint2*)(B0 + nf * 64);
                uint32_t br[2] = {bb.x, bb.y};
                mma16n8k8(acc[0][nf], am0, br);
                mma16n8k8(acc[1][nf], am1, br);
            }
        }
        if (++cs == 4) cs = 0;
    }

    // epilogue: LN1 correction + store z
    float cj[16], dj[16];
    #pragma unroll
    for (int nf = 0; nf < 8; ++nf) {
        int colG = j0 + warpN + nf * 8 + 2 * tig;
        float2 cc = *(const float2*)&g_c[colG];
        float2 dd = *(const float2*)&g_dv[colG];
        cj[nf * 2] = cc.x; cj[nf * 2 + 1] = cc.y;
        dj[nf * 2] = dd.x; dj[nf * 2 + 1] = dd.y;
    }
    #pragma unroll
    for (int mi = 0; mi < 2; ++mi) {
        #pragma unroll
        for (int h = 0; h < 2; ++h) {
            int row = m0 + warpM + mi * 16 + h * 8 + gid;
            float mu = g_mean[row];
            float rs = g_rstd[row];
            float* zp = g_z + (size_t)row * DR + j0 + warpN;
            #pragma unroll
            for (int nf = 0; nf < 8; ++nf) {
                float v0 = acc[mi][nf][h * 2 + 0];
                float v1 = acc[mi][nf][h * 2 + 1];
                float2 o;
                o.x = rs * (v0 - mu * cj[nf * 2 + 0]) + dj[nf * 2 + 0];
                o.y = rs * (v1 - mu * cj[nf * 2 + 1]) + dj[nf * 2 + 1];
                *(float2*)&zp[nf * 8 + 2 * tig] = o;
            }
        }
    }
}

// ---------------- MoE: 64-row tiles, (2-row x 4-h) blocking ----------------
#define MOE_SMEM_FLOATS (64 * 257 + 8192 + 256 + 256 + 256 + 4 + 4)

__global__ __launch_bounds__(256, 2) void moe_kernel(const float* __restrict__ g2,
                                                     const float* __restrict__ b2g,
                                                     const float* __restrict__ w1,
                                                     const float* __restrict__ b1e) {
    extern __shared__ float sm[];
    float* yf    = sm;                  // 64 x 257
    float* w1s   = yf + 64 * 257;       // 8192
    float* g2s   = w1s + 8192;          // 256
    float* b2s   = g2s + 256;           // 256
    float* gates = b2s + 256;           // 64 x 4
    float* sImp  = gates + 256;
    float* sLoad = sImp + 4;
    __shared__ float betas[4];

    int tid = threadIdx.x, lane = tid & 31, w = tid >> 5;
    int m0 = blockIdx.x * 64;

    g2s[tid] = g2[tid];
    b2s[tid] = b2g[tid];
    if (tid < 4) betas[tid] = g_scal[14 + tid];
    if (tid < 8) { sImp[tid & 3] = 0.f; sLoad[tid & 3] = 0.f; }
    __syncthreads();

    for (int rr = 0; rr < 8; ++rr) {
        int r = w * 8 + rr;
        int m = m0 + r;
        const float* zr = g_z + (size_t)m * DR;
        float ev[8];
        float s = 0.f, sq = 0.f;
        #pragma unroll
        for (int i = 0; i < 8; ++i) {
            float v = zr[lane + 32 * i];
            ev[i] = v; s += v; sq += v * v;
        }
        s = wsum(s); sq = wsum(sq);
        float muv = s * (1.f / 256.f);
        float rsv = rsqrtf(sq * (1.f / 256.f) - muv * muv + 1e-5f);
        #pragma unroll
        for (int i = 0; i < 8; ++i) {
            int j = lane + 32 * i;
            yf[r * 257 + j] = (ev[i] - muv) * rsv * g2s[j] + b2s[j];
        }
        if (lane == 0) {
            float4 al = g_alpha4[m];
            float lv[4] = {rsv * al.x + betas[0], rsv * al.y + betas[1],
                           rsv * al.z + betas[2], rsv * al.w + betas[3]};
            int i0 = 0; float v0 = lv[0];
            #pragma unroll
            for (int e = 1; e < 4; ++e) if (lv[e] > v0) { v0 = lv[e]; i0 = e; }
            int i1 = -1; float v1 = -1e30f;
            #pragma unroll
            for (int e = 0; e < 4; ++e) if (e != i0 && lv[e] > v1) { v1 = lv[e]; i1 = e; }
            float ex = __expf(v1 - v0);
            float inv = 1.f / (1.f + ex);
            float ga = inv, gb = ex * inv;
            gates[r * 4 + 0] = 0.f; gates[r * 4 + 1] = 0.f;
            gates[r * 4 + 2] = 0.f; gates[r * 4 + 3] = 0.f;
            gates[r * 4 + i0] = ga;
            gates[r * 4 + i1] = gb;
            atomicAdd(&sImp[i0], ga);  atomicAdd(&sImp[i1], gb);
            atomicAdd(&sLoad[i0], 1.f); atomicAdd(&sLoad[i1], 1.f);
        }
    }
    __syncthreads();
    if (tid < 4) {
        atomicAdd(&g_imp[tid], sImp[tid]);
        atomicAdd(&g_load[tid], sLoad[tid]);
    }

    int rp = tid >> 3;          // 0..31 row-pair
    int hq = (tid & 7) * 4;     // hidden base
    int ra = rp * 2, rb = ra + 1;
    float rowPXa = 0.f, rowPTa = 0.f, rowPXb = 0.f, rowPTb = 0.f;
    for (int e = 0; e < NE; ++e) {
        __syncthreads();
        const float* w1p = w1 + (size_t)e * (DR * DH);
        #pragma unroll
        for (int q = 0; q < 32; ++q) w1s[tid + 256 * q] = w1p[tid + 256 * q];
        __syncthreads();
        float fa[4], fb[4];
        #pragma unroll
        for (int i = 0; i < 4; ++i) {
            float bv = b1e[e * DH + hq + i];
            fa[i] = bv; fb[i] = bv;
        }
        const float* yra = yf + ra * 257;
        const float* yrb = yf + rb * 257;
        #pragma unroll 4
        for (int k = 0; k < 256; ++k) {
            float ya = yra[k], yb = yrb[k];
            float4 wv = *(const float4*)&w1s[k * 32 + hq];
            fa[0] += ya * wv.x; fa[1] += ya * wv.y; fa[2] += ya * wv.z; fa[3] += ya * wv.w;
            fb[0] += yb * wv.x; fb[1] += yb * wv.y; fb[2] += yb * wv.z; fb[3] += yb * wv.w;
        }
        float pxa = 0.f, pta = 0.f, pxb = 0.f, ptb = 0.f;
        #pragma unroll
        for (int i = 0; i < 4; ++i) {
            float wx = g_w2bar[(e * 2 + 0) * DH + hq + i];
            float wt = g_w2bar[(e * 2 + 1) * DH + hq + i];
            float ha = fmaxf(fa[i], 0.f), hb = fmaxf(fb[i], 0.f);
            pxa += ha * wx; pta += ha * wt;
            pxb += hb * wx; ptb += hb * wt;
        }
        #pragma unroll
        for (int o = 1; o < 8; o <<= 1) {
            pxa += __shfl_xor_sync(0xffffffffu, pxa, o);
            pta += __shfl_xor_sync(0xffffffffu, pta, o);
            pxb += __shfl_xor_sync(0xffffffffu, pxb, o);
            ptb += __shfl_xor_sync(0xffffffffu, ptb, o);
        }
        float gva = gates[ra * 4 + e], gvb = gates[rb * 4 + e];
        rowPXa += gva * (pxa + g_b2bar[e * 2 + 0]);
        rowPTa += gva * (pta + g_b2bar[e * 2 + 1]);
        rowPXb += gvb * (pxb + g_b2bar[e * 2 + 0]);
        rowPTb += gvb * (ptb + g_b2bar[e * 2 + 1]);
    }
    if ((tid & 7) == 0) {
        g_px[m0 + ra] = 1.f / (1.f + expf(-rowPXa));
        g_pt[m0 + ra] = 1.f / (1.f + expf(-rowPTa));
        g_px[m0 + rb] = 1.f / (1.f + expf(-rowPXb));
        g_pt[m0 + rb] = 1.f / (1.f + expf(-rowPTb));
    }
}

// ---------------- aux loss (scalar) ----------------
__global__ void aux_kernel(float* auxp) {
    if (threadIdx.x == 0) {
        float mi = 0.f, ml = 0.f;
        #pragma unroll
        for (int e = 0; e < NE; ++e) { mi += g_imp[e]; ml += g_load[e]; }
        mi *= 0.25f; ml *= 0.25f;
        float vi = 0.f, vl = 0.f;
        #pragma unroll
        for (int e = 0; e < NE; ++e) {
            float a = g_imp[e] - mi; vi += a * a;
            float b = g_load[e] - ml; vl += b * b;
        }
        vi *= 0.25f; vl *= 0.25f;
        auxp[0] = vi / (mi * mi + 1e-10f) + vl / (ml * ml + 1e-10f);
    }
}

// ---------------- out_x/out_t + |diff| reduction (lane-consecutive) ----------------
__global__ void outxt_kernel(const float* __restrict__ x, const float* __restrict__ t,
                             const float* __restrict__ past_x, const float* __restrict__ past_t,
                             const float* __restrict__ modal, const int* __restrict__ taskp,
                             float* __restrict__ ox, float* __restrict__ ot) {
    int tid = threadIdx.x;
    int nt = blockIdx.x;  // 128 n-tiles of 16
    int b = blockIdx.y;   // 8
    int task = taskp[0];
    float msx[4], mst[4], A1[4], A2[4];
    const float* mx = modal + (size_t)(task * 2 + 0) * DIMC;
    const float* mt = modal + (size_t)(task * 2 + 1) * DIMC;
    #pragma unroll
    for (int q = 0; q < 4; ++q) {
        msx[q] = mx[tid + 256 * q];
        mst[q] = mt[tid + 256 * q];
        A1[q] = 0.f; A2[q] = 0.f;
    }
    for (int nn = 0; nn < 16; ++nn) {
        size_t m = (size_t)b * NN + nt * 16 + nn;
        size_t row = m * DIMC;
        float p1 = g_px[m], p2 = g_pt[m];
        #pragma unroll
        for (int q = 0; q < 4; ++q) {
            size_t idx = row + tid + 256 * q;
            float vx = p1 * x[idx] + msx[q];
            float vt = p2 * t[idx] + mst[q];
            ox[idx] = vx;
            ot[idx] = vt;
            A1[q] += fabsf(vx - past_x[idx]);
            A2[q] += fabsf(vt - past_t[idx]);
        }
    }
    #pragma unroll
    for (int q = 0; q < 4; ++q) {
        atomicAdd(&g_dd[0][b * DIMC + tid + 256 * q], A1[q]);
        atomicAdd(&g_dd[1][b * DIMC + tid + 256 * q], A2[q]);
    }
}

// ---------------- scoreA: hidden = d @ ws1 partials ----------------
__global__ void scoreA_kernel(const float* __restrict__ ws1) {
    __shared__ float ds[2][8][128];
    int tid = threadIdx.x;
    int ic = blockIdx.x;
    int jc = blockIdx.y;
    for (int q = tid; q < 2048; q += 256) {
        int s = q >> 10, rem = q & 1023;
        int bb = rem >> 7, i = rem & 127;
        ds[s][bb][i] = g_dd[s][bb * DIMC + ic * 128 + i] * (1.f / 2048.f);
    }
    __syncthreads();
    int j = jc * 256 + tid;
    float acc0[8], acc1[8];
    #pragma unroll
    for (int bb = 0; bb < 8; ++bb) { acc0[bb] = 0.f; acc1[bb] = 0.f; }
    const float* wp = ws1 + (size_t)(ic * 128) * DIMC + j;
    #pragma unroll 4
    for (int i = 0; i < 128; ++i) {
        float wv = wp[(size_t)i * DIMC];
        #pragma unroll
        for (int bb = 0; bb < 8; ++bb) {
            acc0[bb] += ds[0][bb][i] * wv;
            acc1[bb] += ds[1][bb][i] * wv;
        }
    }
    #pragma unroll
    for (int bb = 0; bb < 8; ++bb) {
        atomicAdd(&g_racc[0][bb][j], acc0[bb]);
        atomicAdd(&g_racc[1][bb][j], acc1[bb]);
    }
}

// ---------------- scoreB: s = relu(hidden) @ ws2 ----------------
__global__ void scoreB_kernel(const float* __restrict__ ws2) {
    __shared__ float r1s[256], r2s[256];
    int b = blockIdx.x, tid = threadIdx.x;
    float s1 = 0.f, s2 = 0.f;
    #pragma unroll
    for (int q = 0; q < 4; ++q) {
        int j = tid + 256 * q;
        float w2v = ws2[j];
        s1 += fmaxf(g_racc[0][b][j], 0.f) * w2v;
        s2 += fmaxf(g_racc[1][b][j], 0.f) * w2v;
    }
    r1s[tid] = s1; r2s[tid] = s2;
    __syncthreads();
    for (int o = 128; o; o >>= 1) {
        if (tid < o) { r1s[tid] += r1s[tid + o]; r2s[tid] += r2s[tid + o]; }
        __syncthreads();
    }
    if (tid == 0) { g_sv[b][0] = r1s[0]; g_sv[b][1] = r2s[0]; }
}

// ---------------- final combine: recompute from aligned x,t ----------------
__global__ void combine_kernel(const float* __restrict__ x, const float* __restrict__ t,
                               const float* __restrict__ modal, const int* __restrict__ taskp,
                               float* __restrict__ out) {
    int tid = threadIdx.x;
    int nt = blockIdx.x;   // 64 tiles of 32 rows
    int b = blockIdx.y;    // 8
    int task = taskp[0];
    float s1 = g_sv[b][0], s2 = g_sv[b][1];
    float mx = fmaxf(s1, s2);
    float e1 = expf(s1 - mx), e2 = expf(s2 - mx);
    float inv = 1.f / (e1 + e2);
    float w0 = e1 * inv, w1 = e2 * inv;
    float4 msx = ((const float4*)(modal + (size_t)(task * 2 + 0) * DIMC))[tid];
    float4 mst = ((const float4*)(modal + (size_t)(task * 2 + 1) * DIMC))[tid];
    float4 cm;
    cm.x = w1 * msx.x + w0 * mst.x; cm.y = w1 * msx.y + w0 * mst.y;
    cm.z = w1 * msx.z + w0 * mst.z; cm.w = w1 * msx.w + w0 * mst.w;
    for (int nn = 0; nn < 32; ++nn) {
        size_t m = (size_t)b * NN + nt * 32 + nn;
        size_t ro = m * (DIMC / 4) + tid;
        float c1 = w1 * g_px[m], c2 = w0 * g_pt[m];
        float4 xv = ((const float4*)x)[ro];
        float4 tv = ((const float4*)t)[ro];
        float4 o;
        o.x = c1 * xv.x + c2 * tv.x + cm.x;
        o.y = c1 * xv.y + c2 * tv.y + cm.y;
        o.z = c1 * xv.z + c2 * tv.z + cm.z;
        o.w = c1 * xv.w + c2 * tv.w + cm.w;
        ((float4*)out)[ro] = o;
    }
}

// ---------------- launch (gemm at launch index 3 -> ncu-profiled) ----------------
extern "C" void kernel_launch(void* const* d_in, const int* in_sizes, int n_in,
                              void* d_out, int out_size) {
    const float* x      = (const float*)d_in[0];
    const float* t      = (const float*)d_in[1];
    const float* past_x = (const float*)d_in[2];
    const float* past_t = (const float*)d_in[3];
    const int*   taskp  = (const int*)  d_in[4];
    const float* ln1_g  = (const float*)d_in[5];
    const float* ln1_b  = (const float*)d_in[6];
    const float* w_red  = (const float*)d_in[7];
    const float* ln2_g  = (const float*)d_in[8];
    const float* ln2_b  = (const float*)d_in[9];
    const float* w_gate = (const float*)d_in[10];
    const float* w1     = (const float*)d_in[11];
    const float* b1e    = (const float*)d_in[12];
    const float* w2     = (const float*)d_in[13];
    const float* b2     = (const float*)d_in[14];
    const float* modal  = (const float*)d_in[15];
    const float* ws1    = (const float*)d_in[16];
    const float* ws2    = (const float*)d_in[17];

    float* out = (float*)d_out;
    const size_t OUTN = (size_t)MTOK * DIMC;
    bool full = ((size_t)(unsigned)out_size >= 3 * OUTN + 1);

    float *ox, *ot;
    if (full) {
        ox = out + OUTN + 1;     // layout: out | aux | out_x | out_t (4B-aligned only!)
        ot = ox + OUTN;
    } else {
        void* p;
        cudaGetSymbolAddress(&p, g_ox); ox = (float*)p;
        cudaGetSymbolAddress(&p, g_ot); ot = (float*)p;
    }

    prep1_kernel<<<64, 256>>>(w_red, ln1_g, ln1_b);                               // idx 0
    prep2_kernel<<<256, 256>>>(w_red, ln1_g, w_gate, taskp, ln2_g, ln2_b, w2, b2); // idx 1
    rowlogits_kernel<<<256, 256>>>(x, t);                                         // idx 2

    cudaFuncSetAttribute(gemm_tf32_kernel, cudaFuncAttributeMaxDynamicSharedMemorySize,
                         GEMM_SMEM_BYTES);
    gemm_tf32_kernel<<<dim3(2, 128), 256, GEMM_SMEM_BYTES>>>(x, t);               // idx 3 <- profiled

    const int moe_smem = MOE_SMEM_FLOATS * (int)sizeof(float);
    cudaFuncSetAttribute(moe_kernel, cudaFuncAttributeMaxDynamicSharedMemorySize, moe_smem);
    moe_kernel<<<256, 256, moe_smem>>>(ln2_g, ln2_b, w1, b1e);                    // idx 4

    if (full) aux_kernel<<<1, 32>>>(out + OUTN);
    outxt_kernel<<<dim3(128, 8), 256>>>(x, t, past_x, past_t, modal, taskp, ox, ot);
    scoreA_kernel<<<dim3(8, 4), 256>>>(ws1);
    scoreB_kernel<<<8, 256>>>(ws2);
    combine_kernel<<<dim3(64, 8), 256>>>(x, t, modal, taskp, out);
}